// round 15
// baseline (speedup 1.0000x reference)
#include <cuda_runtime.h>

// Problem constants (fixed by setup_inputs)
#define NUM_CLASSES 19
#define BATCH 16
#define HH 1024
#define WW 2048
#define GSZ 8
#define HB (HH / GSZ)             // 128
#define WB (WW / GSZ)             // 256
#define NBLOCKS (BATCH * HB * WB) // 524288
#define TPB 256
#define NCTA (NBLOCKS / TPB)      // 2048
#define WARPS (TPB / 32)
#define FULL 0xffffffffu

// Allocation-free scratch (device globals are the sanctioned workaround).
__device__ unsigned g_masks[NBLOCKS];   // 2 MB: per-tile presence masks
__device__ float    g_partials[NCTA];
__device__ unsigned g_count = 0;

// ---------- Kernel 1: pure target stream -> presence masks ----------
// Measured ~6.7 TB/s (LTS cap) when run as a pure stream. Do not mix.
__global__ void __launch_bounds__(TPB)
fsenc_mask_kernel(const int* __restrict__ targets)
{
    const int tid  = threadIdx.x;
    const int w    = tid >> 5;
    const int lane = tid & 31;

    // Warp covers 32 consecutive tiles [T0, T0+32), one (b, hb) stripe.
    const int T0  = blockIdx.x * TPB + (w << 5);
    const int wb0 = T0 & (WB - 1);
    const int t2  = T0 >> 8;          // / WB
    const int hb  = t2 & (HB - 1);
    const int b   = t2 >> 7;          // / HB

    const int* tb = targets + ((size_t)b * HH + (size_t)hb * GSZ) * WW
                            + (size_t)wb0 * GSZ;

    // Lane-adjacent int4: each instr covers 512B contiguous (4 lines).
    unsigned maskA = 0u, maskB = 0u;
    #pragma unroll
    for (int r = 0; r < GSZ; r++) {
        const int4* p = reinterpret_cast<const int4*>(tb + (size_t)r * WW);
        int4 a = __ldcs(p + lane);        // ints [4L,4L+4)   -> tile L/2
        int4 c = __ldcs(p + 32 + lane);   // ints [128+4L,..) -> tile 16+L/2
        maskA |= (1u << a.x) | (1u << a.y) | (1u << a.z) | (1u << a.w);
        maskB |= (1u << c.x) | (1u << c.y) | (1u << c.z) | (1u << c.w);
    }
    // lanes 2t,2t+1 jointly cover a tile: pair-OR, even lanes store.
    const unsigned ma = maskA | __shfl_xor_sync(FULL, maskA, 1);
    const unsigned mb = maskB | __shfl_xor_sync(FULL, maskB, 1);
    if ((lane & 1) == 0) {
        g_masks[T0 + (lane >> 1)]      = ma;   // tiles [0,16)
        g_masks[T0 + 16 + (lane >> 1)] = mb;   // tiles [16,32)
    }
}

// ---------- Kernel 2: pure pred stream (coalesced float4) + masks ----------
__global__ void __launch_bounds__(TPB)
fsenc_loss_kernel(const float* __restrict__ preds,
                  float* __restrict__ out)
{
    __shared__ unsigned mask_sm[WARPS][32];
    __shared__ float warpsum[WARPS];
    __shared__ double dsm[TPB];
    __shared__ bool isLast;

    const int tid  = threadIdx.x;
    const int w    = tid >> 5;
    const int lane = tid & 31;
    const int T0   = blockIdx.x * TPB + (w << 5);

    // Masks: one coalesced 4B load per lane (L2-hot from K1), publish to smem.
    mask_sm[w][lane] = g_masks[T0 + lane];
    __syncwarp();

    // Preds: warp's 32 tiles = 608 floats = 152 lane-adjacent float4
    // (16B aligned since T0 % 32 == 0). ~20 L1tex wavefronts vs 361 scalar.
    const float4* p4 =
        reinterpret_cast<const float4*>(preds + (size_t)T0 * NUM_CLASSES);
    float s = 0.0f;
    #pragma unroll
    for (int i = 0; i < 5; i++) {
        const int idx    = lane + 32 * i;
        const bool valid = (idx < 152);
        const int idxc   = valid ? idx : 0;
        float4 fv = __ldcs(p4 + idxc);
        const float v[4] = {fv.x, fv.y, fv.z, fv.w};
        float part = 0.0f;
        #pragma unroll
        for (int k = 0; k < 4; k++) {
            const int g   = 4 * idxc + k;      // warp-local float idx [0,608)
            const int tl  = g / NUM_CLASSES;   // owning tile (const-div)
            const int cls = g - tl * NUM_CLASSES;
            const unsigned m = mask_sm[w][tl]; // broadcast-friendly LDS
            const float x  = v[k];
            const float sp = fmaxf(x, 0.0f) + __logf(1.0f + __expf(-fabsf(x)));
            part += sp - (((m >> cls) & 1u) ? x : 0.0f);
        }
        s += valid ? part : 0.0f;
    }

    // Block reduce
    #pragma unroll
    for (int o = 16; o > 0; o >>= 1)
        s += __shfl_xor_sync(FULL, s, o);
    if (lane == 0) warpsum[w] = s;
    __syncthreads();

    if (tid == 0) {
        float vsum = 0.0f;
        #pragma unroll
        for (int i = 0; i < WARPS; i++) vsum += warpsum[i];
        g_partials[blockIdx.x] = vsum;
        __threadfence();
        unsigned n = atomicAdd(&g_count, 1u);
        isLast = (n == NCTA - 1);
    }
    __syncthreads();

    // Last block: deterministic final reduce + mean
    if (isLast) {
        double d = 0.0;
        for (int i = tid; i < NCTA; i += TPB)
            d += (double)__ldcg(&g_partials[i]);
        dsm[tid] = d;
        __syncthreads();
        #pragma unroll
        for (int st = TPB / 2; st > 0; st >>= 1) {
            if (tid < st) dsm[tid] += dsm[tid + st];
            __syncthreads();
        }
        if (tid == 0) {
            out[0] = (float)(dsm[0] / ((double)NBLOCKS * (double)NUM_CLASSES));
            g_count = 0;   // reset for next graph replay
        }
    }
}

extern "C" void kernel_launch(void* const* d_in, const int* in_sizes, int n_in,
                              void* d_out, int out_size)
{
    const float* preds   = (const float*)d_in[0];
    const int*   targets = (const int*)d_in[1];
    // d_in[2] = grid_size (known constant 8)

    fsenc_mask_kernel<<<NCTA, TPB>>>(targets);
    fsenc_loss_kernel<<<NCTA, TPB>>>(preds, (float*)d_out);
}

// round 16
// speedup vs baseline: 1.0339x; 1.0339x over previous
#include <cuda_runtime.h>

// Problem constants (fixed by setup_inputs)
#define NUM_CLASSES 19
#define BATCH 16
#define HH 1024
#define WW 2048
#define GSZ 8
#define HB (HH / GSZ)             // 128
#define WB (WW / GSZ)             // 256
#define NBLOCKS (BATCH * HB * WB) // 524288
#define TPB 256
#define NCTA (NBLOCKS / TPB)      // 2048
#define WARPS (TPB / 32)
#define FULL 0xffffffffu
#define CTA_FLOATS (TPB * NUM_CLASSES)      // 4864 floats per CTA
#define CTA_VEC4   (CTA_FLOATS / 4)         // 1216 float4

// Allocation-free scratch (device globals are the sanctioned workaround).
__device__ unsigned g_masks[NBLOCKS];   // 2 MB: per-tile presence masks
__device__ float    g_partials[NCTA];
__device__ unsigned g_count = 0;

// ---------- Kernel 1: pure target stream -> presence masks ----------
// Measured ~6.7 TB/s (LTS cap) as a pure stream. Unchanged from R14.
__global__ void __launch_bounds__(TPB)
fsenc_mask_kernel(const int* __restrict__ targets)
{
    const int tid  = threadIdx.x;
    const int w    = tid >> 5;
    const int lane = tid & 31;

    const int T0  = blockIdx.x * TPB + (w << 5);
    const int wb0 = T0 & (WB - 1);
    const int t2  = T0 >> 8;          // / WB
    const int hb  = t2 & (HB - 1);
    const int b   = t2 >> 7;          // / HB

    const int* tb = targets + ((size_t)b * HH + (size_t)hb * GSZ) * WW
                            + (size_t)wb0 * GSZ;

    unsigned maskA = 0u, maskB = 0u;
    #pragma unroll
    for (int r = 0; r < GSZ; r++) {
        const int4* p = reinterpret_cast<const int4*>(tb + (size_t)r * WW);
        int4 a = __ldcs(p + lane);        // ints [4L,4L+4)   -> tile L/2
        int4 c = __ldcs(p + 32 + lane);   // ints [128+4L,..) -> tile 16+L/2
        maskA |= (1u << a.x) | (1u << a.y) | (1u << a.z) | (1u << a.w);
        maskB |= (1u << c.x) | (1u << c.y) | (1u << c.z) | (1u << c.w);
    }
    const unsigned ma = maskA | __shfl_xor_sync(FULL, maskA, 1);
    const unsigned mb = maskB | __shfl_xor_sync(FULL, maskB, 1);
    if ((lane & 1) == 0) {
        g_masks[T0 + (lane >> 1)]      = ma;   // tiles [0,16)
        g_masks[T0 + 16 + (lane >> 1)] = mb;   // tiles [16,32)
    }
}

// ---------- Kernel 2: lean pred pass ----------
// Coalesced float4 -> smem stage; thread-per-tile consume with register mask.
// Identity: softplus(x) - bit*x = relu(x ^ (bit<<31)) + log1p(exp(-|x|)).
__global__ void __launch_bounds__(TPB)
fsenc_loss_kernel(const float* __restrict__ preds,
                  float* __restrict__ out)
{
    __shared__ float sp[CTA_FLOATS];        // 19456 B pred stage
    __shared__ float warpsum[WARPS];
    __shared__ double dsm[TPB];
    __shared__ bool isLast;

    const int tid  = threadIdx.x;
    const int w    = tid >> 5;
    const int lane = tid & 31;
    const int B0   = blockIdx.x * TPB;      // first tile of this CTA

    // Mask for this thread's tile: coalesced 4B load (L2-hot from K1).
    const unsigned mask = __ldg(&g_masks[B0 + tid]);

    // Stage CTA's 4864 pred floats: 1216 coalesced float4 (16B aligned).
    const float4* p4 =
        reinterpret_cast<const float4*>(preds + (size_t)B0 * NUM_CLASSES);
    float4* s4 = reinterpret_cast<float4*>(sp);
    #pragma unroll
    for (int i = 0; i < 5; i++) {
        const int idx = tid + TPB * i;
        if (idx < CTA_VEC4) s4[idx] = __ldcs(p4 + idx);
    }
    __syncthreads();

    // Consume own row: stride-19 across lanes -> conflict-free LDS.
    const float* row = sp + tid * NUM_CLASSES;
    float s = 0.0f;
    #pragma unroll
    for (int c = 0; c < NUM_CLASSES; c++) {
        const float x = row[c];
        // sign-flip x iff class c present (shift amount is compile-time)
        const unsigned sgn = (mask << (31 - c)) & 0x80000000u;
        const float xp = __uint_as_float(__float_as_uint(x) ^ sgn);
        // relu(xp) + log1p(exp(-|x|)); |xp| == |x|
        s += fmaxf(xp, 0.0f) + __logf(1.0f + __expf(-fabsf(xp)));
    }

    // Block reduce
    #pragma unroll
    for (int o = 16; o > 0; o >>= 1)
        s += __shfl_xor_sync(FULL, s, o);
    if (lane == 0) warpsum[w] = s;
    __syncthreads();

    if (tid == 0) {
        float vsum = 0.0f;
        #pragma unroll
        for (int i = 0; i < WARPS; i++) vsum += warpsum[i];
        g_partials[blockIdx.x] = vsum;
        __threadfence();
        unsigned n = atomicAdd(&g_count, 1u);
        isLast = (n == NCTA - 1);
    }
    __syncthreads();

    // Last block: deterministic final reduce + mean
    if (isLast) {
        double d = 0.0;
        for (int i = tid; i < NCTA; i += TPB)
            d += (double)__ldcg(&g_partials[i]);
        dsm[tid] = d;
        __syncthreads();
        #pragma unroll
        for (int st = TPB / 2; st > 0; st >>= 1) {
            if (tid < st) dsm[tid] += dsm[tid + st];
            __syncthreads();
        }
        if (tid == 0) {
            out[0] = (float)(dsm[0] / ((double)NBLOCKS * (double)NUM_CLASSES));
            g_count = 0;   // reset for next graph replay
        }
    }
}

extern "C" void kernel_launch(void* const* d_in, const int* in_sizes, int n_in,
                              void* d_out, int out_size)
{
    const float* preds   = (const float*)d_in[0];
    const int*   targets = (const int*)d_in[1];
    // d_in[2] = grid_size (known constant 8)

    fsenc_mask_kernel<<<NCTA, TPB>>>(targets);
    fsenc_loss_kernel<<<NCTA, TPB>>>(preds, (float*)d_out);
}